// round 14
// baseline (speedup 1.0000x reference)
#include <cuda_runtime.h>
#include <cuda_bf16.h>
#include <math.h>

#define NN 2000
#define NE 8000
#define BB 16
#define TT 512
#define NVV 7
#define BN_ 112
#define LL 64
#define DM 128
#define NH 8
#define DK 16
#define DLLM 768
#define STOK 1000
#define SP 1008   // padded token count (63 chunks of 16)

// ---------------- scratch layout (floats) ----------------
//   GE   : 0        (12288)
//   ENC  : 12288    (917504)
//   Qb   : 929792   (917504)
//   REP  : 1847296  (917504)
//   KP   : 2764800  (6*129024 = 774144)
//   VP   : 3538944  (774144)
//   K2b  : 4313088  (16128 floats)  [h][1008][16perm] bf16
//   V2b  : 4329216  (16128 floats)  [h][16][63][16perm] bf16
__device__ float g_scratch[4345344];

// ================= mma / async helpers =================
__device__ __forceinline__ void mma16816(float& d0, float& d1, float& d2, float& d3,
    unsigned a0, unsigned a1, unsigned a2, unsigned a3, unsigned b0, unsigned b1) {
    asm volatile("mma.sync.aligned.m16n8k16.row.col.f32.bf16.bf16.f32 "
        "{%0,%1,%2,%3}, {%4,%5,%6,%7}, {%8,%9}, {%0,%1,%2,%3};"
        : "+f"(d0), "+f"(d1), "+f"(d2), "+f"(d3)
        : "r"(a0), "r"(a1), "r"(a2), "r"(a3), "r"(b0), "r"(b1));
}
__device__ __forceinline__ void mma_tf32(float* d,
    const unsigned* a, const unsigned* b) {
    asm volatile("mma.sync.aligned.m16n8k8.row.col.f32.tf32.tf32.f32 "
        "{%0,%1,%2,%3}, {%4,%5,%6,%7}, {%8,%9}, {%0,%1,%2,%3};"
        : "+f"(d[0]), "+f"(d[1]), "+f"(d[2]), "+f"(d[3])
        : "r"(a[0]), "r"(a[1]), "r"(a[2]), "r"(a[3]), "r"(b[0]), "r"(b[1]));
}
__device__ __forceinline__ unsigned cvt2(float lo, float hi) {
    unsigned d;
    asm("cvt.rn.bf16x2.f32 %0, %1, %2;" : "=r"(d) : "f"(hi), "f"(lo));
    return d;
}
__device__ __forceinline__ unsigned f2tf32(float v) {
    unsigned r;
    asm("cvt.rna.tf32.f32 %0, %1;" : "=r"(r) : "f"(v));
    return r;
}
__device__ __forceinline__ void cp16(float* dst, const float* src, bool pred) {
    unsigned d = (unsigned)__cvta_generic_to_shared(dst);
    int sz = pred ? 16 : 0;
    asm volatile("cp.async.cg.shared.global [%0], [%1], 16, %2;"
                 :: "r"(d), "l"(src), "r"(sz));
}
#define CP_COMMIT() asm volatile("cp.async.commit_group;" ::: "memory")
#define CP_WAIT1()  asm volatile("cp.async.wait_group 1;" ::: "memory")
#define CP_WAIT0()  asm volatile("cp.async.wait_group 0;" ::: "memory")

// pair-interleave permutation: row order [0,1,8,9, 2,3,10,11, 4,5,12,13, 6,7,14,15]
__device__ __forceinline__ int perm16(int j) {
    return ((j >> 1) & 3) * 4 + ((j >> 3) << 1) + (j & 1);
}

// ---------------- GAT -> graph_emb (validated; 1024 threads) ----------------
__global__ void gat_kernel(const float* __restrict__ x_all, const float* __restrict__ W,
                           const float* __restrict__ a_src, const float* __restrict__ a_dst,
                           const float* __restrict__ bias, const void* __restrict__ ei_raw,
                           float* __restrict__ graph_emb) {
    extern __shared__ float sm[];
    float*    s_src = sm;
    float*    s_dst = s_src + NN;
    unsigned* maxu  = (unsigned*)(s_dst + NN);
    float*    denom = (float*)(maxu + NN);
    float*    ex    = denom + NN;
    float*    uv    = ex + NE;
    float*    gacc  = uv + 6;

    int b = blockIdx.x, tid = threadIdx.x;
    const float* x = x_all + (size_t)b * NN * 3;
    const long long* ei64 = (const long long*)ei_raw;
    const int*       ei32 = (const int*)ei_raw;

    __shared__ int s_is64;
    if (tid == 0) {
        int ok = 1;
        #pragma unroll
        for (int e = 0; e < 16; e++) {
            long long v = ei64[e];
            if (v < 0 || v >= NN) ok = 0;
        }
        s_is64 = ok;
    }
    if (tid < 6) uv[tid] = 0.f;
    if (tid < 3) gacc[tid] = 0.f;
    __syncthreads();
    const bool is64 = (s_is64 != 0);

    {
        float p[6] = {0,0,0,0,0,0};
        for (int d = tid; d < DLLM; d += blockDim.x) {
            float as = a_src[d], ad = a_dst[d];
            #pragma unroll
            for (int c = 0; c < 3; c++) {
                float w = W[c*DLLM + d];
                p[c]   += w * as;
                p[3+c] += w * ad;
            }
        }
        #pragma unroll
        for (int off = 16; off; off >>= 1)
            #pragma unroll
            for (int c = 0; c < 6; c++) p[c] += __shfl_xor_sync(0xffffffffu, p[c], off);
        if ((tid & 31) == 0)
            #pragma unroll
            for (int c = 0; c < 6; c++) atomicAdd(&uv[c], p[c]);
    }
    __syncthreads();
    float u0 = uv[0], u1 = uv[1], u2 = uv[2];
    float v0 = uv[3], v1 = uv[4], v2 = uv[5];

    for (int i = tid; i < NN; i += blockDim.x) {
        float x0 = x[i*3], x1 = x[i*3+1], x2 = x[i*3+2];
        s_src[i] = x0*u0 + x1*u1 + x2*u2;
        s_dst[i] = x0*v0 + x1*v1 + x2*v2;
        maxu[i]  = 0u;
        denom[i] = 0.f;
    }
    __syncthreads();

    for (int e = tid; e < NE; e += blockDim.x) {
        int s = is64 ? (int)ei64[e]      : ei32[e];
        int d = is64 ? (int)ei64[NE + e] : ei32[NE + e];
        if ((unsigned)s >= NN || (unsigned)d >= NN) { ex[e] = 0.f; continue; }
        float z  = s_src[s] + s_dst[d];
        float lg = z > 0.f ? z : 0.2f * z;
        ex[e] = lg;
        unsigned bits = __float_as_uint(lg);
        unsigned key  = (bits & 0x80000000u) ? ~bits : (bits | 0x80000000u);
        atomicMax(&maxu[d], key);
    }
    __syncthreads();

    for (int e = tid; e < NE; e += blockDim.x) {
        int d = is64 ? (int)ei64[NE + e] : ei32[NE + e];
        if ((unsigned)d >= NN) continue;
        unsigned key  = maxu[d];
        unsigned bits = (key & 0x80000000u) ? (key & 0x7FFFFFFFu) : ~key;
        float m = __uint_as_float(bits);
        float p = expf(ex[e] - m);
        ex[e] = p;
        atomicAdd(&denom[d], p);
    }
    __syncthreads();

    {
        float g0 = 0.f, g1 = 0.f, g2 = 0.f;
        for (int e = tid; e < NE; e += blockDim.x) {
            int s = is64 ? (int)ei64[e]      : ei32[e];
            int d = is64 ? (int)ei64[NE + e] : ei32[NE + e];
            if ((unsigned)s >= NN || (unsigned)d >= NN) continue;
            float alpha = ex[e] / (denom[d] + 1e-16f);
            g0 += alpha * x[s*3];
            g1 += alpha * x[s*3+1];
            g2 += alpha * x[s*3+2];
        }
        #pragma unroll
        for (int off = 16; off; off >>= 1) {
            g0 += __shfl_xor_sync(0xffffffffu, g0, off);
            g1 += __shfl_xor_sync(0xffffffffu, g1, off);
            g2 += __shfl_xor_sync(0xffffffffu, g2, off);
        }
        if ((tid & 31) == 0) {
            atomicAdd(&gacc[0], g0);
            atomicAdd(&gacc[1], g1);
            atomicAdd(&gacc[2], g2);
        }
    }
    __syncthreads();

    float G0 = gacc[0] * (1.f/NN), G1 = gacc[1] * (1.f/NN), G2 = gacc[2] * (1.f/NN);
    for (int d = tid; d < DLLM; d += blockDim.x)
        graph_emb[b*DLLM + d] = G0*W[d] + G1*W[DLLM + d] + G2*W[2*DLLM + d] + bias[d];
}

// ---------------- fused normalize + patch conv ----------------
__global__ void normenc_kernel(const float* __restrict__ x_enc, const float* __restrict__ convW,
                               float* __restrict__ enc) {
    __shared__ float ssm[520];
    __shared__ float wsm[48 * 128];
    int bv = blockIdx.x;
    int b = bv / NVV, v = bv % NVV;
    int tid = threadIdx.x, lane = tid & 31, warp = tid >> 5;
    const float* xp = x_enc + (size_t)b * TT * NVV + v;

    for (int i = tid; i < 48 * 128; i += 256) {
        int pj = i >> 7, m = i & 127;
        wsm[i] = convW[m * 48 + pj];
    }
    for (int t = tid; t < TT; t += 256) ssm[t] = xp[(size_t)t * NVV];
    __syncthreads();

    float s = 0.f, s2 = 0.f;
    for (int t = tid; t < TT; t += 256) {
        float val = ssm[t];
        s += val; s2 += val * val;
    }
    #pragma unroll
    for (int off = 16; off; off >>= 1) {
        s  += __shfl_xor_sync(0xffffffffu, s,  off);
        s2 += __shfl_xor_sync(0xffffffffu, s2, off);
    }
    __shared__ float rs[8], rs2[8];
    if (lane == 0) { rs[warp] = s; rs2[warp] = s2; }
    __syncthreads();
    __shared__ float sh_mean, sh_inv;
    if (tid == 0) {
        float ts = 0.f, ts2 = 0.f;
        for (int w = 0; w < 8; w++) { ts += rs[w]; ts2 += rs2[w]; }
        float mean = ts / (float)TT;
        float var  = ts2 / (float)TT - mean * mean;
        sh_mean = mean;
        sh_inv  = 1.f / sqrtf(var + 1e-5f);
    }
    __syncthreads();
    float mean = sh_mean, inv = sh_inv;
    for (int t = tid; t < TT; t += 256) ssm[t] = (ssm[t] - mean) * inv;
    __syncthreads();
    if (tid < 8) ssm[TT + tid] = ssm[TT - 1];
    __syncthreads();

    for (int idx = tid; idx < LL * DM; idx += 256) {
        int l = idx >> 7, m = idx & 127;
        float acc = 0.f;
        #pragma unroll
        for (int j = 0; j < 3; j++) {
            int lj = l + j - 1;
            lj = (lj < 0) ? LL - 1 : (lj >= LL ? 0 : lj);
            int base = lj * 8;
            #pragma unroll
            for (int p = 0; p < 16; p++)
                acc += wsm[(p*3 + j) * 128 + m] * ssm[base + p];
        }
        enc[(size_t)bv * LL * DM + idx] = acc;
    }
}

// ================= shared tf32 tile compute (panel K=64, row pad 68) =================
__device__ __forceinline__ void tf32_panel(const float* As, const float* Bs,
                                           int wr, int wc, int g, int tg,
                                           float acc[2][4][4]) {
    #pragma unroll
    for (int ks = 0; ks < 8; ks++) {
        int k = ks * 8;
        unsigned a[2][4], bfr[4][2];
        #pragma unroll
        for (int rf = 0; rf < 2; rf++) {
            int m0 = wr * 32 + rf * 16;
            a[rf][0] = f2tf32(As[(m0 + g)     * 68 + k + tg]);
            a[rf][1] = f2tf32(As[(m0 + g + 8) * 68 + k + tg]);
            a[rf][2] = f2tf32(As[(m0 + g)     * 68 + k + tg + 4]);
            a[rf][3] = f2tf32(As[(m0 + g + 8) * 68 + k + tg + 4]);
        }
        #pragma unroll
        for (int cf = 0; cf < 4; cf++) {
            int n0 = wc * 32 + cf * 8;
            bfr[cf][0] = f2tf32(Bs[(n0 + g) * 68 + k + tg]);
            bfr[cf][1] = f2tf32(Bs[(n0 + g) * 68 + k + tg + 4]);
        }
        #pragma unroll
        for (int rf = 0; rf < 2; rf++)
            #pragma unroll
            for (int cf = 0; cf < 4; cf++)
                mma_tf32(acc[rf][cf], a[rf], bfr[cf]);
    }
}

__device__ __forceinline__ void fill_panel(float* As, float* Bs,
                                           const float* A, const float* B,
                                           int bm, int bn, int koff, int ldA, int ldB,
                                           int Mlim, int tid) {
    for (int i = tid; i < 2048; i += 256) {
        int row = i >> 4, c4 = i & 15;
        int grow = bm + row;
        cp16(&As[row * 68 + c4 * 4],
             A + (size_t)grow * ldA + koff + c4 * 4, grow < Mlim);
    }
    for (int i = tid; i < 1024; i += 256) {
        int row = i >> 4, c4 = i & 15;
        cp16(&Bs[row * 68 + c4 * 4],
             B + (size_t)(bn + row) * ldB + koff + c4 * 4, true);
    }
    CP_COMMIT();
}

// ---------------- tf32 GEMM (pipelined): C = A @ B^T + bias (+GE) ----------------
template<bool ADD_GE>
__global__ void __launch_bounds__(256) gemm_tf32(const float* __restrict__ A,
                                                 const float* __restrict__ B,
                                                 const float* __restrict__ bias,
                                                 float* __restrict__ C,
                                                 int M, int N, int K,
                                                 const float* __restrict__ GE) {
    extern __shared__ __align__(16) float smG[];
    float* As[2] = { smG, smG + 128 * 68 };
    float* Bs[2] = { smG + 2 * 128 * 68, smG + 2 * 128 * 68 + 64 * 68 };
    int bm = blockIdx.y * 128, bn = blockIdx.x * 64;
    int tid = threadIdx.x;
    int w = tid >> 5, lane = tid & 31;
    int wr = w & 3, wc = w >> 2;
    int g = lane >> 2, tg = lane & 3;

    float acc[2][4][4];
    #pragma unroll
    for (int rf = 0; rf < 2; rf++)
        #pragma unroll
        for (int cf = 0; cf < 4; cf++)
            #pragma unroll
            for (int i = 0; i < 4; i++) acc[rf][cf][i] = 0.f;

    int P = K >> 6;
    fill_panel(As[0], Bs[0], A, B, bm, bn, 0, K, K, M, tid);
    for (int p = 0; p < P; p++) {
        if (p + 1 < P)
            fill_panel(As[(p+1)&1], Bs[(p+1)&1], A, B, bm, bn, (p+1)*64, K, K, M, tid);
        if (p + 1 < P) { CP_WAIT1(); } else { CP_WAIT0(); }
        __syncthreads();
        tf32_panel(As[p&1], Bs[p&1], wr, wc, g, tg, acc);
        __syncthreads();
    }

    #pragma unroll
    for (int rf = 0; rf < 2; rf++) {
        int row0 = bm + wr * 32 + rf * 16 + g;
        int row1 = row0 + 8;
        const float* ge0 = ADD_GE ? (GE + (row0 / (NVV * LL)) * DLLM) : nullptr;
        const float* ge1 = ADD_GE ? (GE + (row1 / (NVV * LL)) * DLLM) : nullptr;
        #pragma unroll
        for (int cf = 0; cf < 4; cf++) {
            int col = bn + wc * 32 + cf * 8 + 2 * tg;
            float b0 = bias[col], b1 = bias[col + 1];
            float v00 = acc[rf][cf][0] + b0, v01 = acc[rf][cf][1] + b1;
            float v10 = acc[rf][cf][2] + b0, v11 = acc[rf][cf][3] + b1;
            if (ADD_GE) {
                v00 += ge0[col]; v01 += ge0[col + 1];
                v10 += ge1[col]; v11 += ge1[col + 1];
            }
            *(float2*)(C + (size_t)row0 * N + col) = make_float2(v00, v01);
            *(float2*)(C + (size_t)row1 * N + col) = make_float2(v10, v11);
        }
    }
}

// ---------------- K/V projection, tf32 split-K, pipelined ----------------
// grid (2 Ntile, 8 Mtile, 12): z -> kv = z/6, chunk = z%6 (K range [chunk*128,+128), 2 panels)
__global__ void __launch_bounds__(256) kvproj_tf32(const float* __restrict__ A,
                                                   const float* __restrict__ Bk,
                                                   const float* __restrict__ Bv,
                                                   float* __restrict__ KP,
                                                   float* __restrict__ VP) {
    extern __shared__ __align__(16) float smG[];
    float* As[2] = { smG, smG + 128 * 68 };
    float* Bs[2] = { smG + 2 * 128 * 68, smG + 2 * 128 * 68 + 64 * 68 };
    int kv = blockIdx.z / 6, chunk = blockIdx.z % 6;
    const float* B = kv ? Bv : Bk;
    float* P = (kv ? VP : KP) + chunk * (SP * 128);
    int bm = blockIdx.y * 128, bn = blockIdx.x * 64;
    int tid = threadIdx.x;
    int w = tid >> 5, lane = tid & 31;
    int wr = w & 3, wc = w >> 2;
    int g = lane >> 2, tg = lane & 3;

    float acc[2][4][4];
    #pragma unroll
    for (int rf = 0; rf < 2; rf++)
        #pragma unroll
        for (int cf = 0; cf < 4; cf++)
            #pragma unroll
            for (int i = 0; i < 4; i++) acc[rf][cf][i] = 0.f;

    int k0 = chunk * 128;
    fill_panel(As[0], Bs[0], A, B, bm, bn, k0, DLLM, DLLM, STOK, tid);
    #pragma unroll 1
    for (int p = 0; p < 2; p++) {
        if (p + 1 < 2)
            fill_panel(As[(p+1)&1], Bs[(p+1)&1], A, B, bm, bn, k0 + (p+1)*64,
                       DLLM, DLLM, STOK, tid);
        if (p + 1 < 2) { CP_WAIT1(); } else { CP_WAIT0(); }
        __syncthreads();
        tf32_panel(As[p&1], Bs[p&1], wr, wc, g, tg, acc);
        __syncthreads();
    }

    #pragma unroll
    for (int rf = 0; rf < 2; rf++) {
        int row0 = bm + wr * 32 + rf * 16 + g;
        int row1 = row0 + 8;
        #pragma unroll
        for (int cf = 0; cf < 4; cf++) {
            int col = bn + wc * 32 + cf * 8 + 2 * tg;
            if (row0 < STOK)
                *(float2*)(P + (size_t)row0 * 128 + col) =
                    make_float2(acc[rf][cf][0], acc[rf][cf][1]);
            if (row1 < STOK)
                *(float2*)(P + (size_t)row1 * 128 + col) =
                    make_float2(acc[rf][cf][2], acc[rf][cf][3]);
        }
    }
}

// ---------------- reduce split-K (6 chunks) + bias -> bf16 mma layouts ----------------
__global__ void kv_reduce(const float* __restrict__ KP, const float* __restrict__ VP,
                          const float* __restrict__ kb, const float* __restrict__ vb,
                          __nv_bfloat16* __restrict__ K2b, __nv_bfloat16* __restrict__ V2b) {
    int idx = blockIdx.x * 256 + threadIdx.x;   // < 2*1008*128 = 258048
    int bufi = idx / 129024;
    int rr = idx - bufi * 129024;
    int s = rr >> 7, c = rr & 127;
    float acc = 0.f;
    if (s < STOK) {
        const float* P = bufi ? VP : KP;
        acc = (bufi ? vb : kb)[c];
        #pragma unroll
        for (int ch = 0; ch < 6; ch++) acc += P[ch * 129024 + s * 128 + c];
    }
    int h = c >> 4, e = c & 15;
    __nv_bfloat16 v = __float2bfloat16(acc);
    if (bufi == 0) {
        K2b[(size_t)h * SP * 16 + s * 16 + perm16(e)] = v;
    } else {
        int cc = s >> 4, js = s & 15;
        V2b[(size_t)h * SP * 16 + e * SP + cc * 16 + perm16(js)] = v;
    }
}

// ---------------- attention via bf16 mma, 2 bn per block ----------------
// grid (NH, BN_/2), 128 threads. K/V smem fill amortized over 2 Q-tiles.
__global__ void __launch_bounds__(128) attn_mma(const float* __restrict__ Q,
                                                const __nv_bfloat16* __restrict__ K2b,
                                                const __nv_bfloat16* __restrict__ V2b,
                                                float* __restrict__ rep) {
    extern __shared__ __align__(16) char smA[];
    __nv_bfloat16* Ks = (__nv_bfloat16*)smA;        // [1008][16]
    __nv_bfloat16* Vs = Ks + SP * 16;               // [16][1008]
    int h = blockIdx.x, bn0 = blockIdx.y * 2;
    int tid = threadIdx.x, w = tid >> 5, lane = tid & 31;
    int g = lane >> 2, tg = lane & 3;

    {
        const uint4* ksrc = (const uint4*)(K2b + (size_t)h * SP * 16);
        const uint4* vsrc = (const uint4*)(V2b + (size_t)h * SP * 16);
        uint4* kdst = (uint4*)Ks;
        uint4* vdst = (uint4*)Vs;
        for (int i = tid; i < 2016; i += 128) { kdst[i] = ksrc[i]; vdst[i] = vsrc[i]; }
    }
    __syncthreads();

    const float QS = 0.25f * 1.4426950408889634f;

    #pragma unroll 1
    for (int bi = 0; bi < 2; bi++) {
        int bn = bn0 + bi;
        const float* qb = Q + ((size_t)(bn * LL + w * 16 + g)) * 128 + h * 16;
        float2 q00 = *(const float2*)(qb + 2*tg);
        float2 q01 = *(const float2*)(qb + 2*tg + 8);
        float2 q10 = *(const float2*)(qb + 8*128 + 2*tg);
        float2 q11 = *(const float2*)(qb + 8*128 + 2*tg + 8);
        unsigned a0 = cvt2(QS*q00.x, QS*q00.y);
        unsigned a1 = cvt2(QS*q10.x, QS*q10.y);
        unsigned a2 = cvt2(QS*q01.x, QS*q01.y);
        unsigned a3 = cvt2(QS*q11.x, QS*q11.y);

        float o0=0,o1=0,o2=0,o3=0,o4=0,o5=0,o6=0,o7=0;
        float rs0 = 0.f, rs1 = 0.f;

        #pragma unroll 1
        for (int c = 0; c < 63; c++) {
            int s0 = c * 16;
            uint2 kb0 = *(const uint2*)(Ks + (s0 + g) * 16 + tg * 4);
            uint2 kb1 = *(const uint2*)(Ks + (s0 + 8 + g) * 16 + tg * 4);
            float s00=0,s01=0,s02=0,s03=0, s10=0,s11=0,s12=0,s13=0;
            mma16816(s00,s01,s02,s03, a0,a1,a2,a3, kb0.x, kb0.y);
            mma16816(s10,s11,s12,s13, a0,a1,a2,a3, kb1.x, kb1.y);

            int c0 = s0 + 2*tg;
            int c1 = s0 + 8 + 2*tg;
            float p00 = (c0     < STOK) ? exp2f(s00) : 0.f;
            float p01 = (c0 + 1 < STOK) ? exp2f(s01) : 0.f;
            float p02 = (c0     < STOK) ? exp2f(s02) : 0.f;
            float p03 = (c0 + 1 < STOK) ? exp2f(s03) : 0.f;
            float p10 = (c1     < STOK) ? exp2f(s10) : 0.f;
            float p11 = (c1 + 1 < STOK) ? exp2f(s11) : 0.f;
            float p12 = (c1     < STOK) ? exp2f(s12) : 0.f;
            float p13 = (c1 + 1 < STOK) ? exp2f(s13) : 0.f;
            rs0 += p00 + p01 + p10 + p11;
            rs1 += p02 + p03 + p12 + p13;

            unsigned pa0 = cvt2(p00, p01);
            unsigned pa1 = cvt2(p02, p03);
            unsigned pa2 = cvt2(p10, p11);
            unsigned pa3 = cvt2(p12, p13);

            uint2 vb0 = *(const uint2*)(Vs + g * SP + s0 + tg * 4);
            uint2 vb1 = *(const uint2*)(Vs + (g + 8) * SP + s0 + tg * 4);
            mma16816(o0,o1,o2,o3, pa0,pa1,pa2,pa3, vb0.x, vb0.y);
            mma16816(o4,o5,o6,o7, pa0,pa1,pa2,pa3, vb1.x, vb1.y);
        }

        rs0 += __shfl_xor_sync(0xffffffffu, rs0, 1);
        rs0 += __shfl_xor_sync(0xffffffffu, rs0, 2);
        rs1 += __shfl_xor_sync(0xffffffffu, rs1, 1);
        rs1 += __shfl_xor_sync(0xffffffffu, rs1, 2);
        float inv0 = 1.f / rs0, inv1 = 1.f / rs1;

        float* ob = rep + ((size_t)(bn * LL + w * 16 + g)) * 128 + h * 16;
        *(float2*)(ob + 2*tg)             = make_float2(o0 * inv0, o1 * inv0);
        *(float2*)(ob + 2*tg + 8)         = make_float2(o4 * inv0, o5 * inv0);
        *(float2*)(ob + 8*128 + 2*tg)     = make_float2(o2 * inv1, o3 * inv1);
        *(float2*)(ob + 8*128 + 2*tg + 8) = make_float2(o6 * inv1, o7 * inv1);
    }
}

// ---------------- launch ----------------
extern "C" void kernel_launch(void* const* d_in, const int* in_sizes, int n_in,
                              void* d_out, int out_size) {
    const float* node_input = (const float*)d_in[0];
    const float* gat_W      = (const float*)d_in[1];
    const float* gat_a_src  = (const float*)d_in[2];
    const float* gat_a_dst  = (const float*)d_in[3];
    const float* gat_bias   = (const float*)d_in[4];
    const float* x_enc      = (const float*)d_in[5];
    const float* conv_W     = (const float*)d_in[6];
    const float* q_W        = (const float*)d_in[7];
    const float* q_b        = (const float*)d_in[8];
    const float* k_W        = (const float*)d_in[9];
    const float* k_b        = (const float*)d_in[10];
    const float* v_W        = (const float*)d_in[11];
    const float* v_b        = (const float*)d_in[12];
    const float* o_W        = (const float*)d_in[13];
    const float* o_b        = (const float*)d_in[14];
    const float* source_emb = (const float*)d_in[15];
    const void*  edge_index = (const void*)d_in[16];
    float* out = (float*)d_out;

    float* base = nullptr;
    cudaGetSymbolAddress((void**)&base, g_scratch);
    float* GE   = base;
    float* ENC  = base + 12288;
    float* Qb   = base + 929792;
    float* REP  = base + 1847296;
    float* KP   = base + 2764800;
    float* VP   = base + 3538944;
    __nv_bfloat16* K2b = (__nv_bfloat16*)(base + 4313088);
    __nv_bfloat16* V2b = (__nv_bfloat16*)(base + 4329216);

    size_t gat_smem  = (size_t)(NN * 4 + NE + 12) * sizeof(float);
    size_t attn_smem = (size_t)(2 * SP * 16) * sizeof(__nv_bfloat16);   // 64512 B
    size_t g32_smem  = (size_t)(2 * (128 + 64) * 68) * sizeof(float);   // 104448 B
    cudaFuncSetAttribute(gat_kernel,       cudaFuncAttributeMaxDynamicSharedMemorySize, (int)gat_smem);
    cudaFuncSetAttribute(attn_mma,         cudaFuncAttributeMaxDynamicSharedMemorySize, (int)attn_smem);
    cudaFuncSetAttribute(gemm_tf32<false>, cudaFuncAttributeMaxDynamicSharedMemorySize, (int)g32_smem);
    cudaFuncSetAttribute(gemm_tf32<true>,  cudaFuncAttributeMaxDynamicSharedMemorySize, (int)g32_smem);
    cudaFuncSetAttribute(kvproj_tf32,      cudaFuncAttributeMaxDynamicSharedMemorySize, (int)g32_smem);

    gat_kernel<<<BB, 1024, gat_smem>>>(node_input, gat_W, gat_a_src, gat_a_dst,
                                       gat_bias, edge_index, GE);
    normenc_kernel<<<BN_, 256>>>(x_enc, conv_W, ENC);
    gemm_tf32<false><<<dim3(2, 56), 256, g32_smem>>>(ENC, q_W, q_b, Qb,
                                                     BN_ * LL, 128, 128, nullptr);
    kvproj_tf32<<<dim3(2, 8, 12), 256, g32_smem>>>(source_emb, k_W, v_W, KP, VP);
    kv_reduce<<<1008, 256>>>(KP, VP, k_b, v_b, K2b, V2b);
    attn_mma<<<dim3(NH, BN_ / 2), 128, attn_smem>>>(Qb, K2b, V2b, REP);
    gemm_tf32<true><<<dim3(12, 56), 256, g32_smem>>>(REP, o_W, o_b, out,
                                                     BN_ * LL, DLLM, 128, GE);
}

// round 15
// speedup vs baseline: 1.0701x; 1.0701x over previous
#include <cuda_runtime.h>
#include <cuda_bf16.h>
#include <math.h>

#define NN 2000
#define NE 8000
#define BB 16
#define TT 512
#define NVV 7
#define BN_ 112
#define LL 64
#define DM 128
#define NH 8
#define DK 16
#define DLLM 768
#define STOK 1000
#define SP 1008   // padded token count (63 chunks of 16)

// ---------------- scratch layout (floats) ----------------
//   GE   : 0        (12288)
//   ENC  : 12288    (917504)
//   Qb   : 929792   (917504)
//   REP  : 1847296  (917504)
//   KP   : 2764800  (3*129024 = 387072)
//   VP   : 3151872  (387072)
//   K2b  : 3538944  (16128 floats)  [h][1008][16perm] bf16
//   V2b  : 3555072  (16128 floats)  [h][16][63][16perm] bf16
__device__ float g_scratch[3571200];

// ================= mma / async helpers =================
__device__ __forceinline__ void mma16816(float& d0, float& d1, float& d2, float& d3,
    unsigned a0, unsigned a1, unsigned a2, unsigned a3, unsigned b0, unsigned b1) {
    asm volatile("mma.sync.aligned.m16n8k16.row.col.f32.bf16.bf16.f32 "
        "{%0,%1,%2,%3}, {%4,%5,%6,%7}, {%8,%9}, {%0,%1,%2,%3};"
        : "+f"(d0), "+f"(d1), "+f"(d2), "+f"(d3)
        : "r"(a0), "r"(a1), "r"(a2), "r"(a3), "r"(b0), "r"(b1));
}
__device__ __forceinline__ void mma_tf32(float* d,
    const unsigned* a, const unsigned* b) {
    asm volatile("mma.sync.aligned.m16n8k8.row.col.f32.tf32.tf32.f32 "
        "{%0,%1,%2,%3}, {%4,%5,%6,%7}, {%8,%9}, {%0,%1,%2,%3};"
        : "+f"(d[0]), "+f"(d[1]), "+f"(d[2]), "+f"(d[3])
        : "r"(a[0]), "r"(a[1]), "r"(a[2]), "r"(a[3]), "r"(b[0]), "r"(b[1]));
}
__device__ __forceinline__ unsigned cvt2(float lo, float hi) {
    unsigned d;
    asm("cvt.rn.bf16x2.f32 %0, %1, %2;" : "=r"(d) : "f"(hi), "f"(lo));
    return d;
}
__device__ __forceinline__ unsigned f2tf32(float v) {
    unsigned r;
    asm("cvt.rna.tf32.f32 %0, %1;" : "=r"(r) : "f"(v));
    return r;
}
__device__ __forceinline__ void cp16(float* dst, const float* src, bool pred) {
    unsigned d = (unsigned)__cvta_generic_to_shared(dst);
    int sz = pred ? 16 : 0;
    asm volatile("cp.async.cg.shared.global [%0], [%1], 16, %2;"
                 :: "r"(d), "l"(src), "r"(sz));
}
#define CP_COMMIT() asm volatile("cp.async.commit_group;" ::: "memory")
#define CP_WAIT1()  asm volatile("cp.async.wait_group 1;" ::: "memory")
#define CP_WAIT0()  asm volatile("cp.async.wait_group 0;" ::: "memory")

// pair-interleave permutation: row order [0,1,8,9, 2,3,10,11, 4,5,12,13, 6,7,14,15]
__device__ __forceinline__ int perm16(int j) {
    return ((j >> 1) & 3) * 4 + ((j >> 3) << 1) + (j & 1);
}

// ---------------- GAT -> graph_emb (validated; 1024 threads) ----------------
__global__ void gat_kernel(const float* __restrict__ x_all, const float* __restrict__ W,
                           const float* __restrict__ a_src, const float* __restrict__ a_dst,
                           const float* __restrict__ bias, const void* __restrict__ ei_raw,
                           float* __restrict__ graph_emb) {
    extern __shared__ float sm[];
    float*    s_src = sm;
    float*    s_dst = s_src + NN;
    unsigned* maxu  = (unsigned*)(s_dst + NN);
    float*    denom = (float*)(maxu + NN);
    float*    ex    = denom + NN;
    float*    uv    = ex + NE;
    float*    gacc  = uv + 6;

    int b = blockIdx.x, tid = threadIdx.x;
    const float* x = x_all + (size_t)b * NN * 3;
    const long long* ei64 = (const long long*)ei_raw;
    const int*       ei32 = (const int*)ei_raw;

    __shared__ int s_is64;
    if (tid == 0) {
        int ok = 1;
        #pragma unroll
        for (int e = 0; e < 16; e++) {
            long long v = ei64[e];
            if (v < 0 || v >= NN) ok = 0;
        }
        s_is64 = ok;
    }
    if (tid < 6) uv[tid] = 0.f;
    if (tid < 3) gacc[tid] = 0.f;
    __syncthreads();
    const bool is64 = (s_is64 != 0);

    {
        float p[6] = {0,0,0,0,0,0};
        for (int d = tid; d < DLLM; d += blockDim.x) {
            float as = a_src[d], ad = a_dst[d];
            #pragma unroll
            for (int c = 0; c < 3; c++) {
                float w = W[c*DLLM + d];
                p[c]   += w * as;
                p[3+c] += w * ad;
            }
        }
        #pragma unroll
        for (int off = 16; off; off >>= 1)
            #pragma unroll
            for (int c = 0; c < 6; c++) p[c] += __shfl_xor_sync(0xffffffffu, p[c], off);
        if ((tid & 31) == 0)
            #pragma unroll
            for (int c = 0; c < 6; c++) atomicAdd(&uv[c], p[c]);
    }
    __syncthreads();
    float u0 = uv[0], u1 = uv[1], u2 = uv[2];
    float v0 = uv[3], v1 = uv[4], v2 = uv[5];

    for (int i = tid; i < NN; i += blockDim.x) {
        float x0 = x[i*3], x1 = x[i*3+1], x2 = x[i*3+2];
        s_src[i] = x0*u0 + x1*u1 + x2*u2;
        s_dst[i] = x0*v0 + x1*v1 + x2*v2;
        maxu[i]  = 0u;
        denom[i] = 0.f;
    }
    __syncthreads();

    for (int e = tid; e < NE; e += blockDim.x) {
        int s = is64 ? (int)ei64[e]      : ei32[e];
        int d = is64 ? (int)ei64[NE + e] : ei32[NE + e];
        if ((unsigned)s >= NN || (unsigned)d >= NN) { ex[e] = 0.f; continue; }
        float z  = s_src[s] + s_dst[d];
        float lg = z > 0.f ? z : 0.2f * z;
        ex[e] = lg;
        unsigned bits = __float_as_uint(lg);
        unsigned key  = (bits & 0x80000000u) ? ~bits : (bits | 0x80000000u);
        atomicMax(&maxu[d], key);
    }
    __syncthreads();

    for (int e = tid; e < NE; e += blockDim.x) {
        int d = is64 ? (int)ei64[NE + e] : ei32[NE + e];
        if ((unsigned)d >= NN) continue;
        unsigned key  = maxu[d];
        unsigned bits = (key & 0x80000000u) ? (key & 0x7FFFFFFFu) : ~key;
        float m = __uint_as_float(bits);
        float p = expf(ex[e] - m);
        ex[e] = p;
        atomicAdd(&denom[d], p);
    }
    __syncthreads();

    {
        float g0 = 0.f, g1 = 0.f, g2 = 0.f;
        for (int e = tid; e < NE; e += blockDim.x) {
            int s = is64 ? (int)ei64[e]      : ei32[e];
            int d = is64 ? (int)ei64[NE + e] : ei32[NE + e];
            if ((unsigned)s >= NN || (unsigned)d >= NN) continue;
            float alpha = ex[e] / (denom[d] + 1e-16f);
            g0 += alpha * x[s*3];
            g1 += alpha * x[s*3+1];
            g2 += alpha * x[s*3+2];
        }
        #pragma unroll
        for (int off = 16; off; off >>= 1) {
            g0 += __shfl_xor_sync(0xffffffffu, g0, off);
            g1 += __shfl_xor_sync(0xffffffffu, g1, off);
            g2 += __shfl_xor_sync(0xffffffffu, g2, off);
        }
        if ((tid & 31) == 0) {
            atomicAdd(&gacc[0], g0);
            atomicAdd(&gacc[1], g1);
            atomicAdd(&gacc[2], g2);
        }
    }
    __syncthreads();

    float G0 = gacc[0] * (1.f/NN), G1 = gacc[1] * (1.f/NN), G2 = gacc[2] * (1.f/NN);
    for (int d = tid; d < DLLM; d += blockDim.x)
        graph_emb[b*DLLM + d] = G0*W[d] + G1*W[DLLM + d] + G2*W[2*DLLM + d] + bias[d];
}

// ---------------- fused normalize + patch conv ----------------
__global__ void normenc_kernel(const float* __restrict__ x_enc, const float* __restrict__ convW,
                               float* __restrict__ enc) {
    __shared__ float ssm[520];
    __shared__ float wsm[48 * 128];
    int bv = blockIdx.x;
    int b = bv / NVV, v = bv % NVV;
    int tid = threadIdx.x, lane = tid & 31, warp = tid >> 5;
    const float* xp = x_enc + (size_t)b * TT * NVV + v;

    for (int i = tid; i < 48 * 128; i += 256) {
        int pj = i >> 7, m = i & 127;
        wsm[i] = convW[m * 48 + pj];
    }
    for (int t = tid; t < TT; t += 256) ssm[t] = xp[(size_t)t * NVV];
    __syncthreads();

    float s = 0.f, s2 = 0.f;
    for (int t = tid; t < TT; t += 256) {
        float val = ssm[t];
        s += val; s2 += val * val;
    }
    #pragma unroll
    for (int off = 16; off; off >>= 1) {
        s  += __shfl_xor_sync(0xffffffffu, s,  off);
        s2 += __shfl_xor_sync(0xffffffffu, s2, off);
    }
    __shared__ float rs[8], rs2[8];
    if (lane == 0) { rs[warp] = s; rs2[warp] = s2; }
    __syncthreads();
    __shared__ float sh_mean, sh_inv;
    if (tid == 0) {
        float ts = 0.f, ts2 = 0.f;
        for (int w = 0; w < 8; w++) { ts += rs[w]; ts2 += rs2[w]; }
        float mean = ts / (float)TT;
        float var  = ts2 / (float)TT - mean * mean;
        sh_mean = mean;
        sh_inv  = 1.f / sqrtf(var + 1e-5f);
    }
    __syncthreads();
    float mean = sh_mean, inv = sh_inv;
    for (int t = tid; t < TT; t += 256) ssm[t] = (ssm[t] - mean) * inv;
    __syncthreads();
    if (tid < 8) ssm[TT + tid] = ssm[TT - 1];
    __syncthreads();

    for (int idx = tid; idx < LL * DM; idx += 256) {
        int l = idx >> 7, m = idx & 127;
        float acc = 0.f;
        #pragma unroll
        for (int j = 0; j < 3; j++) {
            int lj = l + j - 1;
            lj = (lj < 0) ? LL - 1 : (lj >= LL ? 0 : lj);
            int base = lj * 8;
            #pragma unroll
            for (int p = 0; p < 16; p++)
                acc += wsm[(p*3 + j) * 128 + m] * ssm[base + p];
        }
        enc[(size_t)bv * LL * DM + idx] = acc;
    }
}

// ================= shared tf32 tile compute (panel K=32, row pad 36) =================
__device__ __forceinline__ void tf32_panel(const float* As, const float* Bs,
                                           int wr, int wc, int g, int tg,
                                           float acc[2][4][4]) {
    #pragma unroll
    for (int ks = 0; ks < 4; ks++) {
        int k = ks * 8;
        unsigned a[2][4], bfr[4][2];
        #pragma unroll
        for (int rf = 0; rf < 2; rf++) {
            int m0 = wr * 32 + rf * 16;
            a[rf][0] = f2tf32(As[(m0 + g)     * 36 + k + tg]);
            a[rf][1] = f2tf32(As[(m0 + g + 8) * 36 + k + tg]);
            a[rf][2] = f2tf32(As[(m0 + g)     * 36 + k + tg + 4]);
            a[rf][3] = f2tf32(As[(m0 + g + 8) * 36 + k + tg + 4]);
        }
        #pragma unroll
        for (int cf = 0; cf < 4; cf++) {
            int n0 = wc * 32 + cf * 8;
            bfr[cf][0] = f2tf32(Bs[(n0 + g) * 36 + k + tg]);
            bfr[cf][1] = f2tf32(Bs[(n0 + g) * 36 + k + tg + 4]);
        }
        #pragma unroll
        for (int rf = 0; rf < 2; rf++)
            #pragma unroll
            for (int cf = 0; cf < 4; cf++)
                mma_tf32(acc[rf][cf], a[rf], bfr[cf]);
    }
}

// panel fill via cp.async: A rows [bm,bm+128) cols [koff,koff+32); B rows [bn,bn+64)
__device__ __forceinline__ void fill_panel(float* As, float* Bs,
                                           const float* A, const float* B,
                                           int bm, int bn, int koff, int ldA, int ldB,
                                           int Mlim, int tid) {
    for (int i = tid; i < 1024; i += 256) {            // A: 128 rows x 8 float4
        int row = i >> 3, c4 = i & 7;
        int grow = bm + row;
        cp16(&As[row * 36 + c4 * 4],
             A + (size_t)grow * ldA + koff + c4 * 4, grow < Mlim);
    }
    for (int i = tid; i < 512; i += 256) {             // B: 64 rows x 8 float4
        int row = i >> 3, c4 = i & 7;
        cp16(&Bs[row * 36 + c4 * 4],
             B + (size_t)(bn + row) * ldB + koff + c4 * 4, true);
    }
    CP_COMMIT();
}

// ---------------- tf32 GEMM (pipelined, K32 panels): C = A @ B^T + bias (+GE) ----------------
// Tile 128(M) x 64(N); K multiple of 32; M mult 128, N mult 64.
template<bool ADD_GE>
__global__ void __launch_bounds__(256) gemm_tf32(const float* __restrict__ A,
                                                 const float* __restrict__ B,
                                                 const float* __restrict__ bias,
                                                 float* __restrict__ C,
                                                 int M, int N, int K,
                                                 const float* __restrict__ GE) {
    extern __shared__ __align__(16) float smG[];
    float* As[2] = { smG, smG + 128 * 36 };
    float* Bs[2] = { smG + 2 * 128 * 36, smG + 2 * 128 * 36 + 64 * 36 };
    int bm = blockIdx.y * 128, bn = blockIdx.x * 64;
    int tid = threadIdx.x;
    int w = tid >> 5, lane = tid & 31;
    int wr = w & 3, wc = w >> 2;
    int g = lane >> 2, tg = lane & 3;

    float acc[2][4][4];
    #pragma unroll
    for (int rf = 0; rf < 2; rf++)
        #pragma unroll
        for (int cf = 0; cf < 4; cf++)
            #pragma unroll
            for (int i = 0; i < 4; i++) acc[rf][cf][i] = 0.f;

    int P = K >> 5;
    fill_panel(As[0], Bs[0], A, B, bm, bn, 0, K, K, M, tid);
    for (int p = 0; p < P; p++) {
        if (p + 1 < P)
            fill_panel(As[(p+1)&1], Bs[(p+1)&1], A, B, bm, bn, (p+1)*32, K, K, M, tid);
        if (p + 1 < P) { CP_WAIT1(); } else { CP_WAIT0(); }
        __syncthreads();
        tf32_panel(As[p&1], Bs[p&1], wr, wc, g, tg, acc);
        __syncthreads();
    }

    #pragma unroll
    for (int rf = 0; rf < 2; rf++) {
        int row0 = bm + wr * 32 + rf * 16 + g;
        int row1 = row0 + 8;
        const float* ge0 = ADD_GE ? (GE + (row0 / (NVV * LL)) * DLLM) : nullptr;
        const float* ge1 = ADD_GE ? (GE + (row1 / (NVV * LL)) * DLLM) : nullptr;
        #pragma unroll
        for (int cf = 0; cf < 4; cf++) {
            int col = bn + wc * 32 + cf * 8 + 2 * tg;
            float b0 = bias[col], b1 = bias[col + 1];
            float v00 = acc[rf][cf][0] + b0, v01 = acc[rf][cf][1] + b1;
            float v10 = acc[rf][cf][2] + b0, v11 = acc[rf][cf][3] + b1;
            if (ADD_GE) {
                v00 += ge0[col]; v01 += ge0[col + 1];
                v10 += ge1[col]; v11 += ge1[col + 1];
            }
            *(float2*)(C + (size_t)row0 * N + col) = make_float2(v00, v01);
            *(float2*)(C + (size_t)row1 * N + col) = make_float2(v10, v11);
        }
    }
}

// ---------------- K/V projection, tf32 split-K, pipelined (K32 panels) ----------------
// grid (2 Ntile, 8 Mtile, 6): z -> kv = z/3, chunk = z%3 (K range [chunk*256,+256), 8 panels)
__global__ void __launch_bounds__(256) kvproj_tf32(const float* __restrict__ A,
                                                   const float* __restrict__ Bk,
                                                   const float* __restrict__ Bv,
                                                   float* __restrict__ KP,
                                                   float* __restrict__ VP) {
    extern __shared__ __align__(16) float smG[];
    float* As[2] = { smG, smG + 128 * 36 };
    float* Bs[2] = { smG + 2 * 128 * 36, smG + 2 * 128 * 36 + 64 * 36 };
    int kv = blockIdx.z / 3, chunk = blockIdx.z % 3;
    const float* B = kv ? Bv : Bk;
    float* P = (kv ? VP : KP) + chunk * (SP * 128);
    int bm = blockIdx.y * 128, bn = blockIdx.x * 64;
    int tid = threadIdx.x;
    int w = tid >> 5, lane = tid & 31;
    int wr = w & 3, wc = w >> 2;
    int g = lane >> 2, tg = lane & 3;

    float acc[2][4][4];
    #pragma unroll
    for (int rf = 0; rf < 2; rf++)
        #pragma unroll
        for (int cf = 0; cf < 4; cf++)
            #pragma unroll
            for (int i = 0; i < 4; i++) acc[rf][cf][i] = 0.f;

    int k0 = chunk * 256;
    fill_panel(As[0], Bs[0], A, B, bm, bn, k0, DLLM, DLLM, STOK, tid);
    #pragma unroll 1
    for (int p = 0; p < 8; p++) {
        if (p + 1 < 8)
            fill_panel(As[(p+1)&1], Bs[(p+1)&1], A, B, bm, bn, k0 + (p+1)*32,
                       DLLM, DLLM, STOK, tid);
        if (p + 1 < 8) { CP_WAIT1(); } else { CP_WAIT0(); }
        __syncthreads();
        tf32_panel(As[p&1], Bs[p&1], wr, wc, g, tg, acc);
        __syncthreads();
    }

    #pragma unroll
    for (int rf = 0; rf < 2; rf++) {
        int row0 = bm + wr * 32 + rf * 16 + g;
        int row1 = row0 + 8;
        #pragma unroll
        for (int cf = 0; cf < 4; cf++) {
            int col = bn + wc * 32 + cf * 8 + 2 * tg;
            if (row0 < STOK)
                *(float2*)(P + (size_t)row0 * 128 + col) =
                    make_float2(acc[rf][cf][0], acc[rf][cf][1]);
            if (row1 < STOK)
                *(float2*)(P + (size_t)row1 * 128 + col) =
                    make_float2(acc[rf][cf][2], acc[rf][cf][3]);
        }
    }
}

// ---------------- reduce split-K (3 chunks) + bias -> bf16 mma layouts ----------------
__global__ void kv_reduce(const float* __restrict__ KP, const float* __restrict__ VP,
                          const float* __restrict__ kb, const float* __restrict__ vb,
                          __nv_bfloat16* __restrict__ K2b, __nv_bfloat16* __restrict__ V2b) {
    int idx = blockIdx.x * 256 + threadIdx.x;   // < 2*1008*128 = 258048
    int bufi = idx / 129024;
    int rr = idx - bufi * 129024;
    int s = rr >> 7, c = rr & 127;
    float acc = 0.f;
    if (s < STOK) {
        const float* P = bufi ? VP : KP;
        acc = (bufi ? vb : kb)[c];
        #pragma unroll
        for (int ch = 0; ch < 3; ch++) acc += P[ch * 129024 + s * 128 + c];
    }
    int h = c >> 4, e = c & 15;
    __nv_bfloat16 v = __float2bfloat16(acc);
    if (bufi == 0) {
        K2b[(size_t)h * SP * 16 + s * 16 + perm16(e)] = v;
    } else {
        int cc = s >> 4, js = s & 15;
        V2b[(size_t)h * SP * 16 + e * SP + cc * 16 + perm16(js)] = v;
    }
}

// ---------------- attention via bf16 mma (m16n8k16), FA-style (R13 proven config) ----------------
// grid (NH, BN_), 128 threads (4 warps, one per 16 L-rows). exp2 softmax.
__global__ void __launch_bounds__(128) attn_mma(const float* __restrict__ Q,
                                                const __nv_bfloat16* __restrict__ K2b,
                                                const __nv_bfloat16* __restrict__ V2b,
                                                float* __restrict__ rep) {
    extern __shared__ __align__(16) char smA[];
    __nv_bfloat16* Ks = (__nv_bfloat16*)smA;        // [1008][16]
    __nv_bfloat16* Vs = Ks + SP * 16;               // [16][1008]
    int h = blockIdx.x, bn = blockIdx.y;
    int tid = threadIdx.x, w = tid >> 5, lane = tid & 31;
    int g = lane >> 2, tg = lane & 3;

    {
        const uint4* ksrc = (const uint4*)(K2b + (size_t)h * SP * 16);
        const uint4* vsrc = (const uint4*)(V2b + (size_t)h * SP * 16);
        uint4* kdst = (uint4*)Ks;
        uint4* vdst = (uint4*)Vs;
        for (int i = tid; i < 2016; i += 128) { kdst[i] = ksrc[i]; vdst[i] = vsrc[i]; }
    }
    __syncthreads();

    const float QS = 0.25f * 1.4426950408889634f;
    const float* qb = Q + ((size_t)(bn * LL + w * 16 + g)) * 128 + h * 16;
    float2 q00 = *(const float2*)(qb + 2*tg);
    float2 q01 = *(const float2*)(qb + 2*tg + 8);
    float2 q10 = *(const float2*)(qb + 8*128 + 2*tg);
    float2 q11 = *(const float2*)(qb + 8*128 + 2*tg + 8);
    unsigned a0 = cvt2(QS*q00.x, QS*q00.y);
    unsigned a1 = cvt2(QS*q10.x, QS*q10.y);
    unsigned a2 = cvt2(QS*q01.x, QS*q01.y);
    unsigned a3 = cvt2(QS*q11.x, QS*q11.y);

    float o0=0,o1=0,o2=0,o3=0,o4=0,o5=0,o6=0,o7=0;
    float rs0 = 0.f, rs1 = 0.f;

    #pragma unroll 1
    for (int c = 0; c < 63; c++) {
        int s0 = c * 16;
        uint2 kb0 = *(const uint2*)(Ks + (s0 + g) * 16 + tg * 4);
        uint2 kb1 = *(const uint2*)(Ks + (s0 + 8 + g) * 16 + tg * 4);
        float s00=0,s01=0,s02=0,s03=0, s10=0,s11=0,s12=0,s13=0;
        mma16816(s00,s01,s02,s03, a0,a1,a2,a3, kb0.x, kb0.y);
        mma16816(s10,s11,s12,s13, a0,a1,a2,a3, kb1.x, kb1.y);

        int c0 = s0 + 2*tg;
        int c1 = s0 + 8 + 2*tg;
        float p00 = (c0     < STOK) ? exp2f(s00) : 0.f;
        float p01 = (c0 + 1 < STOK) ? exp2f(s01) : 0.f;
        float p02 = (c0     < STOK) ? exp2f(s02) : 0.f;
        float p03 = (c0 + 1 < STOK) ? exp2f(s03) : 0.f;
        float p10 = (c1     < STOK) ? exp2f(s10) : 0.f;
        float p11 = (c1 + 1 < STOK) ? exp2f(s11) : 0.f;
        float p12 = (c1     < STOK) ? exp2f(s12) : 0.f;
        float p13 = (c1 + 1 < STOK) ? exp2f(s13) : 0.f;
        rs0 += p00 + p01 + p10 + p11;
        rs1 += p02 + p03 + p12 + p13;

        unsigned pa0 = cvt2(p00, p01);
        unsigned pa1 = cvt2(p02, p03);
        unsigned pa2 = cvt2(p10, p11);
        unsigned pa3 = cvt2(p12, p13);

        uint2 vb0 = *(const uint2*)(Vs + g * SP + s0 + tg * 4);
        uint2 vb1 = *(const uint2*)(Vs + (g + 8) * SP + s0 + tg * 4);
        mma16816(o0,o1,o2,o3, pa0,pa1,pa2,pa3, vb0.x, vb0.y);
        mma16816(o4,o5,o6,o7, pa0,pa1,pa2,pa3, vb1.x, vb1.y);
    }

    rs0 += __shfl_xor_sync(0xffffffffu, rs0, 1);
    rs0 += __shfl_xor_sync(0xffffffffu, rs0, 2);
    rs1 += __shfl_xor_sync(0xffffffffu, rs1, 1);
    rs1 += __shfl_xor_sync(0xffffffffu, rs1, 2);
    float inv0 = 1.f / rs0, inv1 = 1.f / rs1;

    float* ob = rep + ((size_t)(bn * LL + w * 16 + g)) * 128 + h * 16;
    *(float2*)(ob + 2*tg)             = make_float2(o0 * inv0, o1 * inv0);
    *(float2*)(ob + 2*tg + 8)         = make_float2(o4 * inv0, o5 * inv0);
    *(float2*)(ob + 8*128 + 2*tg)     = make_float2(o2 * inv1, o3 * inv1);
    *(float2*)(ob + 8*128 + 2*tg + 8) = make_float2(o6 * inv1, o7 * inv1);
}

// ---------------- launch ----------------
extern "C" void kernel_launch(void* const* d_in, const int* in_sizes, int n_in,
                              void* d_out, int out_size) {
    const float* node_input = (const float*)d_in[0];
    const float* gat_W      = (const float*)d_in[1];
    const float* gat_a_src  = (const float*)d_in[2];
    const float* gat_a_dst  = (const float*)d_in[3];
    const float* gat_bias   = (const float*)d_in[4];
    const float* x_enc      = (const float*)d_in[5];
    const float* conv_W     = (const float*)d_in[6];
    const float* q_W        = (const float*)d_in[7];
    const float* q_b        = (const float*)d_in[8];
    const float* k_W        = (const float*)d_in[9];
    const float* k_b        = (const float*)d_in[10];
    const float* v_W        = (const float*)d_in[11];
    const float* v_b        = (const float*)d_in[12];
    const float* o_W        = (const float*)d_in[13];
    const float* o_b        = (const float*)d_in[14];
    const float* source_emb = (const float*)d_in[15];
    const void*  edge_index = (const void*)d_in[16];
    float* out = (float*)d_out;

    float* base = nullptr;
    cudaGetSymbolAddress((void**)&base, g_scratch);
    float* GE   = base;
    float* ENC  = base + 12288;
    float* Qb   = base + 929792;
    float* REP  = base + 1847296;
    float* KP   = base + 2764800;
    float* VP   = base + 3151872;
    __nv_bfloat16* K2b = (__nv_bfloat16*)(base + 3538944);
    __nv_bfloat16* V2b = (__nv_bfloat16*)(base + 3555072);

    size_t gat_smem  = (size_t)(NN * 4 + NE + 12) * sizeof(float);
    size_t attn_smem = (size_t)(2 * SP * 16) * sizeof(__nv_bfloat16);   // 64512 B
    size_t g32_smem  = (size_t)(2 * (128 + 64) * 36) * sizeof(float);   // 55296 B
    cudaFuncSetAttribute(gat_kernel,       cudaFuncAttributeMaxDynamicSharedMemorySize, (int)gat_smem);
    cudaFuncSetAttribute(attn_mma,         cudaFuncAttributeMaxDynamicSharedMemorySize, (int)attn_smem);
    cudaFuncSetAttribute(gemm_tf32<false>, cudaFuncAttributeMaxDynamicSharedMemorySize, (int)g32_smem);
    cudaFuncSetAttribute(gemm_tf32<true>,  cudaFuncAttributeMaxDynamicSharedMemorySize, (int)g32_smem);
    cudaFuncSetAttribute(kvproj_tf32,      cudaFuncAttributeMaxDynamicSharedMemorySize, (int)g32_smem);

    gat_kernel<<<BB, 1024, gat_smem>>>(node_input, gat_W, gat_a_src, gat_a_dst,
                                       gat_bias, edge_index, GE);
    normenc_kernel<<<BN_, 256>>>(x_enc, conv_W, ENC);
    gemm_tf32<false><<<dim3(2, 56), 256, g32_smem>>>(ENC, q_W, q_b, Qb,
                                                     BN_ * LL, 128, 128, nullptr);
    kvproj_tf32<<<dim3(2, 8, 6), 256, g32_smem>>>(source_emb, k_W, v_W, KP, VP);
    kv_reduce<<<1008, 256>>>(KP, VP, k_b, v_b, K2b, V2b);
    attn_mma<<<dim3(NH, BN_), 128, attn_smem>>>(Qb, K2b, V2b, REP);
    gemm_tf32<true><<<dim3(12, 56), 256, g32_smem>>>(REP, o_W, o_b, out,
                                                     BN_ * LL, DLLM, 128, GE);
}